// round 9
// baseline (speedup 1.0000x reference)
#include <cuda_runtime.h>

// ---------------------------------------------------------------------------
// QuadraticConv2DTranspose via bed-of-nails sparsity.
//   B=8,H=W=32,CIN=COUT=64,k=3,s=2 -> out [8,64,64,64]
// Parity classes (ho%2,wo%2): NT {1,2,2,4} taps -> F {2,5,5,14} features.
// R9 (= R8 resubmitted; R8 bench hit cudaErrorSystemNotReady in harness init,
//     an infra fault prior to any kernel code):
//     launch_bounds(128,4) -> 16 warps/SM (reg-capped 128), CH=2 chunks
//     (32KB smem/CTA), un-duplicated taps (LDS.32 + 1 alu pack per tap).
//     Horner feature-GEMM in packed fp32x2, cp.async double buffering,
//     two 64-thread cin-halves per CTA with named barriers, gmem reduction.
// ---------------------------------------------------------------------------

typedef unsigned long long u64;

__device__ float g_Kc[106496];
__device__ float g_bias[64];

// Horner-ordered feature lists: per tap a: quads (a,b) b=a..NT-1, then lin_a.
__constant__ int c_L[4][14] = {
    {30,49, 0,0,0,0,0,0,0,0,0,0,0,0},
    {24,26,48,35,50, 0,0,0,0,0,0,0,0,0},
    { 9,15,46,42,52, 0,0,0,0,0,0,0,0,0},
    { 0, 2, 6, 8,45,17,21,23,47,39,41,51,44,53}
};
__constant__ int c_off[4] = {0, 8192, 28672, 49152};
__constant__ int c_Fn[4] = {2, 5, 5, 14};

// --------------------------- preprocessing ---------------------------------

__global__ void qct_prep(const float* __restrict__ fk) {
    int idx = blockIdx.x * 256 + threadIdx.x;
    if (blockIdx.x == 0 && threadIdx.x < 64) {
        int o = threadIdx.x;
        float s = 0.f;
#pragma unroll 8
        for (int c = 0; c < 64; c++) s += fk[(54 * 64 + c) * 64 + o];
        g_bias[o] = s;
    }
    if (idx >= 4 * 14 * 4096) return;
    int C = idx / (14 * 4096);
    int r = idx % (14 * 4096);
    int f = r / 4096;
    int co = r % 4096;
    int c = co >> 6, o = co & 63;
    if (f >= c_Fn[C]) return;
    g_Kc[c_off[C] + (c * c_Fn[C] + f) * 64 + o] = fk[(c_L[C][f] * 64 + c) * 64 + o];
}

// --------------------------- helpers ---------------------------------------

__device__ __forceinline__ void fma2(u64& d, u64 a, u64 b) {
    asm("fma.rn.f32x2 %0, %1, %2, %0;" : "+l"(d) : "l"(a), "l"(b));
}
__device__ __forceinline__ u64 pack2f(float v) {
    u64 r;
    unsigned int u = __float_as_uint(v);
    asm("mov.b64 %0, {%1, %1};" : "=l"(r) : "r"(u));
    return r;
}
__device__ __forceinline__ void unpack2(u64 v, float& lo, float& hi) {
    unsigned int a, b;
    asm("mov.b64 {%0, %1}, %2;" : "=r"(a), "=r"(b) : "l"(v));
    lo = __uint_as_float(a);
    hi = __uint_as_float(b);
}
__device__ __forceinline__ void cp16(void* dst_smem, const void* src) {
    unsigned sdst = (unsigned)__cvta_generic_to_shared(dst_smem);
    asm volatile("cp.async.cg.shared.global [%0], [%1], 16;" :: "r"(sdst), "l"(src));
}
#define CP_COMMIT() asm volatile("cp.async.commit_group;")
template <int N>
__device__ __forceinline__ void cp_wait() {
    asm volatile("cp.async.wait_group %0;" :: "n"(N));
}

// --------------------------- class configs ---------------------------------

template <int C> struct Cfg;
template <> struct Cfg<0> {   // (even, even): tap j=4
    static constexpr int PY = 0, PX = 0, F = 2, OFF = 0, NT = 1, NR = 1, NC = 8;
    __host__ __device__ static constexpr int DR(int) { return 0; }
    __host__ __device__ static constexpr int DC(int) { return 0; }
    __host__ __device__ static constexpr int FS(int a) {
        int s = 0; for (int i = 0; i < a; i++) s += NT - i + 1; return s;
    }
};
template <> struct Cfg<1> {   // (even, odd): taps j=3,5
    static constexpr int PY = 0, PX = 1, F = 5, OFF = 8192, NT = 2, NR = 1, NC = 9;
    __host__ __device__ static constexpr int DR(int) { return 0; }
    __host__ __device__ static constexpr int DC(int a) { return a; }
    __host__ __device__ static constexpr int FS(int a) {
        int s = 0; for (int i = 0; i < a; i++) s += NT - i + 1; return s;
    }
};
template <> struct Cfg<2> {   // (odd, even): taps j=1,7
    static constexpr int PY = 1, PX = 0, F = 5, OFF = 28672, NT = 2, NR = 2, NC = 8;
    __host__ __device__ static constexpr int DR(int a) { return a; }
    __host__ __device__ static constexpr int DC(int) { return 0; }
    __host__ __device__ static constexpr int FS(int a) {
        int s = 0; for (int i = 0; i < a; i++) s += NT - i + 1; return s;
    }
};
template <> struct Cfg<3> {   // (odd, odd): taps j=0,2,6,8
    static constexpr int PY = 1, PX = 1, F = 14, OFF = 49152, NT = 4, NR = 2, NC = 9;
    __host__ __device__ static constexpr int DR(int a) { return a >> 1; }
    __host__ __device__ static constexpr int DC(int a) { return a & 1; }
    __host__ __device__ static constexpr int FS(int a) {
        int s = 0; for (int i = 0; i < a; i++) s += NT - i + 1; return s;
    }
};

#define CH 2

// --------------------------- staging ----------------------------------------
// Chunk = 2 cins. Kernel frags (2*F*64 floats) via cp.async; taps stored
// PLAIN f32: sXu[cl][3 rows][34 cols] (un-duplicated, packed at use).

template <int C>
__device__ __forceinline__ void stage(const float* __restrict__ x, float* sK,
                                      float* sXu, const float* gK, int cc0,
                                      int b, int ipair, int th) {
    using Cf = Cfg<C>;
    const float4* src = (const float4*)(gK + cc0 * Cf::F * 64);
    float4* dst = (float4*)sK;
#pragma unroll
    for (int idx = th; idx < 32 * Cf::F; idx += 64)
        cp16(dst + idx, src + idx);
#pragma unroll
    for (int it = 0; it < 2; it++) {
        int idx = th + it * 64;
        if (idx < 99) {
            int rr = idx / 33, cc = idx % 33;
            int r = ipair * 2 + rr;
            float2 v = make_float2(0.f, 0.f);
            if (r < 32 && cc < 32)
                v = *(const float2*)(x + (((b * 32 + r) * 32 + cc) << 6) + cc0);
            sXu[(0 * 3 + rr) * 34 + cc] = v.x;
            sXu[(1 * 3 + rr) * 34 + cc] = v.y;
        }
    }
}

// --------------------------- compute ----------------------------------------
// Horner: contribution = sum_a t_a * ( K_lin_a + sum_{b>=a} t_b * K_ab ).

template <int C>
__device__ __forceinline__ void compute_chunk(const float* sK, const float* sXu,
                                              int ii, int j0, int tx,
                                              u64 acc[8][4]) {
    using Cf = Cfg<C>;
#pragma unroll
    for (int cl = 0; cl < CH; cl++) {
        u64 rowv[Cf::NR][Cf::NC];
#pragma unroll
        for (int r = 0; r < Cf::NR; r++)
#pragma unroll
            for (int c = 0; c < Cf::NC; c++)
                rowv[r][c] = pack2f(sXu[(cl * 3 + ii + r) * 34 + j0 + c]);

        const float* kbase = sK + cl * Cf::F * 64 + 8 * tx;
#pragma unroll
        for (int a = 0; a < Cf::NT; a++) {
            const int fs = Cf::FS(a);
            const int nb = Cf::NT - a;
            const ulonglong2 la = *(const ulonglong2*)(kbase + (fs + nb) * 64);
            const ulonglong2 lb = *(const ulonglong2*)(kbase + (fs + nb) * 64 + 4);
            ulonglong2 qa[4], qb[4];
#pragma unroll
            for (int b = a; b < Cf::NT; b++) {
                qa[b - a] = *(const ulonglong2*)(kbase + (fs + b - a) * 64);
                qb[b - a] = *(const ulonglong2*)(kbase + (fs + b - a) * 64 + 4);
            }
#pragma unroll
            for (int p = 0; p < 8; p++) {
                u64 t0 = la.x, t1 = la.y, t2 = lb.x, t3 = lb.y;
#pragma unroll
                for (int b = Cf::NT - 1; b >= a; b--) {
                    u64 tb = rowv[Cf::DR(b)][p + Cf::DC(b)];
                    fma2(t0, tb, qa[b - a].x);
                    fma2(t1, tb, qa[b - a].y);
                    fma2(t2, tb, qb[b - a].x);
                    fma2(t3, tb, qb[b - a].y);
                }
                u64 ta = rowv[Cf::DR(a)][p + Cf::DC(a)];
                fma2(acc[p][0], ta, t0);
                fma2(acc[p][1], ta, t1);
                fma2(acc[p][2], ta, t2);
                fma2(acc[p][3], ta, t3);
            }
        }
    }
}

// --------------------------- main kernel ------------------------------------
// CTA: 128 threads = two 64-thread cin-halves (h = t>>6). Per half:
// tx = th&7 -> couts 8tx..+7 ; tyy = th>>3 -> 8 pixels at m0 = 8*tyy.
// 16 chunks of 2 cins, double-buffered. Reduction: h=1 stores partials to
// out, __syncthreads, h=0 adds partial + bias.

template <int C>
__device__ __forceinline__ void run_tile(const float* __restrict__ x,
                                         float* __restrict__ out, int tile) {
    using Cf = Cfg<C>;
    constexpr int KSZ = CH * Cf::F * 64;      // kernel chunk floats
    constexpr int TSZ = CH * 3 * 34;          // plain tap floats
    constexpr int BUF = KSZ + TSZ;

    extern __shared__ float sm[];

    const int t = threadIdx.x;
    const int h = t >> 6;
    const int th = t & 63;
    float* base = sm + h * 2 * BUF;

    const int b = tile >> 4;
    const int ipair = tile & 15;
    const int tx = th & 7;
    const int tyy = th >> 3;
    const int m0 = 8 * tyy;
    const int ii = m0 >> 5;
    const int j0 = m0 & 31;

    u64 acc[8][4];
#pragma unroll
    for (int p = 0; p < 8; p++)
#pragma unroll
        for (int q = 0; q < 4; q++) acc[p][q] = 0ull;

    const float* gK = g_Kc + Cf::OFF;
    const int cbase = h * 32;

    stage<C>(x, base, base + KSZ, gK, cbase, b, ipair, th);
    CP_COMMIT();

    for (int ch = 0; ch < 16; ch++) {
        float* cbuf = base + (ch & 1) * BUF;
        float* nbuf = base + ((ch & 1) ^ 1) * BUF;
        if (ch < 15) {
            stage<C>(x, nbuf, nbuf + KSZ, gK, cbase + (ch + 1) * CH, b, ipair, th);
            CP_COMMIT();
            cp_wait<1>();
        } else {
            cp_wait<0>();
        }
        asm volatile("bar.sync %0, 64;" :: "r"(1 + h));
        compute_chunk<C>(cbuf, cbuf + KSZ, ii, j0, tx, acc);
        asm volatile("bar.sync %0, 64;" :: "r"(1 + h));
    }

    // ---- reduction epilogue ----
    const int i = ipair * 2 + ii;
    const int ho = 2 * i + Cf::PY;

    if (h == 1) {   // store partials (cin 32..63)
#pragma unroll
        for (int p = 0; p < 8; p++) {
            const int wo = 2 * (j0 + p) + Cf::PX;
            float v[8];
#pragma unroll
            for (int q = 0; q < 4; q++) unpack2(acc[p][q], v[2 * q], v[2 * q + 1]);
            float* op = out + (((b * 64 + ho) * 64 + wo) << 6) + 8 * tx;
            *(float4*)(op + 0) = make_float4(v[0], v[1], v[2], v[3]);
            *(float4*)(op + 4) = make_float4(v[4], v[5], v[6], v[7]);
        }
    }
    __syncthreads();
    if (h == 0) {   // add partial + bias, final store
        float4 b0 = *(const float4*)(g_bias + 8 * tx);
        float4 b1 = *(const float4*)(g_bias + 8 * tx + 4);
#pragma unroll
        for (int p = 0; p < 8; p++) {
            const int wo = 2 * (j0 + p) + Cf::PX;
            float* op = out + (((b * 64 + ho) * 64 + wo) << 6) + 8 * tx;
            float4 o0 = *(const float4*)(op + 0);
            float4 o1 = *(const float4*)(op + 4);
            float v[8];
#pragma unroll
            for (int q = 0; q < 4; q++) unpack2(acc[p][q], v[2 * q], v[2 * q + 1]);
            *(float4*)(op + 0) = make_float4(v[0] + b0.x + o0.x, v[1] + b0.y + o0.y,
                                             v[2] + b0.z + o0.z, v[3] + b0.w + o0.w);
            *(float4*)(op + 4) = make_float4(v[4] + b1.x + o1.x, v[5] + b1.y + o1.y,
                                             v[6] + b1.z + o1.z, v[7] + b1.w + o1.w);
        }
    }
}

__global__ __launch_bounds__(128, 4) void qct_main(const float* __restrict__ x,
                                                   float* __restrict__ out) {
    int id = blockIdx.x;
    // heavy class 3 first for wave balance
    if (id < 128)      run_tile<3>(x, out, id);
    else if (id < 256) run_tile<1>(x, out, id - 128);
    else if (id < 384) run_tile<2>(x, out, id - 256);
    else               run_tile<0>(x, out, id - 384);
}

// --------------------------- launch ----------------------------------------

extern "C" void kernel_launch(void* const* d_in, const int* in_sizes, int n_in,
                              void* d_out, int out_size) {
    const float* x  = (const float*)d_in[0];
    const float* fk = (const float*)d_in[1];
    if (n_in >= 2 && in_sizes[0] == 55 * 64 * 64) {  // defensive order check
        const float* tmp = x; x = fk; fk = tmp;
    }
    float* out = (float*)d_out;

    qct_prep<<<(4 * 14 * 4096 + 255) / 256, 256>>>(fk);

    // 2 halves x 2 buffers of (kernel chunk + plain taps), sized for class 3
    const int smem_bytes = 4 * (CH * 14 * 64 + CH * 3 * 34) * 4;  // 31936
    cudaFuncSetAttribute(qct_main, cudaFuncAttributeMaxDynamicSharedMemorySize,
                         smem_bytes);
    qct_main<<<512, 128, smem_bytes>>>(x, out);
}

// round 10
// speedup vs baseline: 1.1726x; 1.1726x over previous
#include <cuda_runtime.h>

// ---------------------------------------------------------------------------
// QuadraticConv2DTranspose via bed-of-nails sparsity.
//   B=8,H=W=32,CIN=COUT=64,k=3,s=2 -> out [8,64,64,64]
// Parity classes (ho%2,wo%2): NT {1,2,2,4} taps -> F {2,5,5,14} features.
// R10: retile thread to 16px x 4co (same 64 outputs): kernel frags = one
//      LDS.128 per (cl,f), held IN REGISTERS across the pixel loop; taps as
//      sliding u64 window (LDS.32 + alu pack). L1 wavefronts/cl -31%.
//      (128,3), CH=4 cp.async double buffering, two 64-thr cin-halves,
//      named barriers, gmem partial reduction. Horner packed-fp32x2 math.
// ---------------------------------------------------------------------------

typedef unsigned long long u64;

__device__ float g_Kc[106496];
__device__ float g_bias[64];

// Horner-ordered feature lists: per tap a: quads (a,b) b=a..NT-1, then lin_a.
__constant__ int c_L[4][14] = {
    {30,49, 0,0,0,0,0,0,0,0,0,0,0,0},
    {24,26,48,35,50, 0,0,0,0,0,0,0,0,0},
    { 9,15,46,42,52, 0,0,0,0,0,0,0,0,0},
    { 0, 2, 6, 8,45,17,21,23,47,39,41,51,44,53}
};
__constant__ int c_off[4] = {0, 8192, 28672, 49152};
__constant__ int c_Fn[4] = {2, 5, 5, 14};

// --------------------------- preprocessing ---------------------------------

__global__ void qct_prep(const float* __restrict__ fk) {
    int idx = blockIdx.x * 256 + threadIdx.x;
    if (blockIdx.x == 0 && threadIdx.x < 64) {
        int o = threadIdx.x;
        float s = 0.f;
#pragma unroll 8
        for (int c = 0; c < 64; c++) s += fk[(54 * 64 + c) * 64 + o];
        g_bias[o] = s;
    }
    if (idx >= 4 * 14 * 4096) return;
    int C = idx / (14 * 4096);
    int r = idx % (14 * 4096);
    int f = r / 4096;
    int co = r % 4096;
    int c = co >> 6, o = co & 63;
    if (f >= c_Fn[C]) return;
    g_Kc[c_off[C] + (c * c_Fn[C] + f) * 64 + o] = fk[(c_L[C][f] * 64 + c) * 64 + o];
}

// --------------------------- helpers ---------------------------------------

__device__ __forceinline__ void fma2(u64& d, u64 a, u64 b) {
    asm("fma.rn.f32x2 %0, %1, %2, %0;" : "+l"(d) : "l"(a), "l"(b));
}
__device__ __forceinline__ u64 pack2f(float v) {
    u64 r;
    unsigned int u = __float_as_uint(v);
    asm("mov.b64 %0, {%1, %1};" : "=l"(r) : "r"(u));
    return r;
}
__device__ __forceinline__ void unpack2(u64 v, float& lo, float& hi) {
    unsigned int a, b;
    asm("mov.b64 {%0, %1}, %2;" : "=r"(a), "=r"(b) : "l"(v));
    lo = __uint_as_float(a);
    hi = __uint_as_float(b);
}
__device__ __forceinline__ void cp16(void* dst_smem, const void* src) {
    unsigned sdst = (unsigned)__cvta_generic_to_shared(dst_smem);
    asm volatile("cp.async.cg.shared.global [%0], [%1], 16;" :: "r"(sdst), "l"(src));
}
#define CP_COMMIT() asm volatile("cp.async.commit_group;")
template <int N>
__device__ __forceinline__ void cp_wait() {
    asm volatile("cp.async.wait_group %0;" :: "n"(N));
}

// --------------------------- class configs ---------------------------------
// Tap a at patch offset (DR(a), DC(a)); window spans WR rows x WC cols.
// Horner layout: FS(a)=group start; quad (a,b) at FS(a)+(b-a); lin at
// FS(a)+(NT-a).

template <int C> struct Cfg;
template <> struct Cfg<0> {   // (even, even): tap j=4
    static constexpr int PY = 0, PX = 0, F = 2, OFF = 0, NT = 1, WR = 1, WC = 1;
    __host__ __device__ static constexpr int DR(int) { return 0; }
    __host__ __device__ static constexpr int DC(int) { return 0; }
    __host__ __device__ static constexpr int FS(int a) {
        int s = 0; for (int i = 0; i < a; i++) s += NT - i + 1; return s;
    }
};
template <> struct Cfg<1> {   // (even, odd): taps j=3,5
    static constexpr int PY = 0, PX = 1, F = 5, OFF = 8192, NT = 2, WR = 1, WC = 2;
    __host__ __device__ static constexpr int DR(int) { return 0; }
    __host__ __device__ static constexpr int DC(int a) { return a; }
    __host__ __device__ static constexpr int FS(int a) {
        int s = 0; for (int i = 0; i < a; i++) s += NT - i + 1; return s;
    }
};
template <> struct Cfg<2> {   // (odd, even): taps j=1,7
    static constexpr int PY = 1, PX = 0, F = 5, OFF = 28672, NT = 2, WR = 2, WC = 1;
    __host__ __device__ static constexpr int DR(int a) { return a; }
    __host__ __device__ static constexpr int DC(int) { return 0; }
    __host__ __device__ static constexpr int FS(int a) {
        int s = 0; for (int i = 0; i < a; i++) s += NT - i + 1; return s;
    }
};
template <> struct Cfg<3> {   // (odd, odd): taps j=0,2,6,8
    static constexpr int PY = 1, PX = 1, F = 14, OFF = 49152, NT = 4, WR = 2, WC = 2;
    __host__ __device__ static constexpr int DR(int a) { return a >> 1; }
    __host__ __device__ static constexpr int DC(int a) { return a & 1; }
    __host__ __device__ static constexpr int FS(int a) {
        int s = 0; for (int i = 0; i < a; i++) s += NT - i + 1; return s;
    }
};

#define CH 4

// --------------------------- staging ----------------------------------------
// Chunk = 4 cins. Kernel frags (4*F*64 floats) via cp.async; taps stored
// PLAIN f32: sXu[cl][3 rows][34 cols] (packed to (v,v) at use).

template <int C>
__device__ __forceinline__ void stage(const float* __restrict__ x, float* sK,
                                      float* sXu, const float* gK, int cc0,
                                      int b, int ipair, int th) {
    using Cf = Cfg<C>;
    const float4* src = (const float4*)(gK + cc0 * Cf::F * 64);
    float4* dst = (float4*)sK;
#pragma unroll
    for (int k = 0; k < Cf::F; k++)
        cp16(dst + k * 64 + th, src + k * 64 + th);
#pragma unroll
    for (int it = 0; it < 2; it++) {
        int idx = th + it * 64;
        if (idx < 99) {
            int rr = idx / 33, cc = idx % 33;
            int r = ipair * 2 + rr;
            float4 v = make_float4(0.f, 0.f, 0.f, 0.f);
            if (r < 32 && cc < 32)
                v = *(const float4*)(x + (((b * 32 + r) * 32 + cc) << 6) + cc0);
            sXu[(0 * 3 + rr) * 34 + cc] = v.x;
            sXu[(1 * 3 + rr) * 34 + cc] = v.y;
            sXu[(2 * 3 + rr) * 34 + cc] = v.z;
            sXu[(3 * 3 + rr) * 34 + cc] = v.w;
        }
    }
}

// --------------------------- compute ----------------------------------------
// Per cl: load all F frags (4 couts each) into registers once, then sweep 16
// pixels with a sliding tap window. Horner:
//   contribution = sum_a t_a * ( K_lin_a + sum_{b>=a} t_b * K_ab ).

template <int C>
__device__ __forceinline__ void compute_chunk(const float* sK, const float* sXu,
                                              int ii, int j0, int tx,
                                              u64 acc[16][2]) {
    using Cf = Cfg<C>;
#pragma unroll
    for (int cl = 0; cl < CH; cl++) {
        const float* kb = sK + cl * Cf::F * 64 + 4 * tx;
        ulonglong2 frg[Cf::F];
#pragma unroll
        for (int f = 0; f < Cf::F; f++)
            frg[f] = *(const ulonglong2*)(kb + f * 64);

        const float* tb = sXu + (cl * 3 + ii) * 34 + j0;

        u64 win[Cf::WR][Cf::WC];
#pragma unroll
        for (int r = 0; r < Cf::WR; r++)
#pragma unroll
            for (int c = 0; c < Cf::WC; c++)
                win[r][c] = pack2f(tb[r * 34 + c]);

#pragma unroll
        for (int p = 0; p < 16; p++) {
#pragma unroll
            for (int a = 0; a < Cf::NT; a++) {
                const int fs = Cf::FS(a);
                const int nb = Cf::NT - a;
                u64 t0 = frg[fs + nb].x;
                u64 t1 = frg[fs + nb].y;
#pragma unroll
                for (int b = Cf::NT - 1; b >= a; b--) {
                    u64 tv = win[Cf::DR(b)][Cf::DC(b)];
                    fma2(t0, tv, frg[fs + b - a].x);
                    fma2(t1, tv, frg[fs + b - a].y);
                }
                u64 ta = win[Cf::DR(a)][Cf::DC(a)];
                fma2(acc[p][0], ta, t0);
                fma2(acc[p][1], ta, t1);
            }
            if (p < 15) {
#pragma unroll
                for (int r = 0; r < Cf::WR; r++) {
#pragma unroll
                    for (int c = 0; c < Cf::WC - 1; c++) win[r][c] = win[r][c + 1];
                    win[r][Cf::WC - 1] = pack2f(tb[r * 34 + p + Cf::WC]);
                }
            }
        }
    }
}

// --------------------------- main kernel ------------------------------------
// CTA: 128 threads = two 64-thread cin-halves (h = t>>6). Per half:
// tx = th&15 -> couts 4tx..+3 ; tyy = th>>4 -> 16 pixels at m0 = 16*tyy.
// 8 chunks of 4 cins, double-buffered. Reduction: h=1 stores partials to
// out, __syncthreads, h=0 adds partial + bias.

template <int C>
__device__ __forceinline__ void run_tile(const float* __restrict__ x,
                                         float* __restrict__ out, int tile) {
    using Cf = Cfg<C>;
    constexpr int KSZ = CH * Cf::F * 64;      // kernel chunk floats
    constexpr int TSZ = CH * 3 * 34;          // plain tap floats
    constexpr int BUF = KSZ + TSZ;

    extern __shared__ float sm[];

    const int t = threadIdx.x;
    const int h = t >> 6;
    const int th = t & 63;
    float* base = sm + h * 2 * BUF;

    const int b = tile >> 4;
    const int ipair = tile & 15;
    const int tx = th & 15;
    const int tyy = th >> 4;                // 0..3
    const int m0 = 16 * tyy;                // first of 16 pixels
    const int ii = m0 >> 5;                 // input row within pair
    const int j0 = m0 & 31;                 // 0 or 16

    u64 acc[16][2];
#pragma unroll
    for (int p = 0; p < 16; p++) { acc[p][0] = 0ull; acc[p][1] = 0ull; }

    const float* gK = g_Kc + Cf::OFF;
    const int cbase = h * 32;

    stage<C>(x, base, base + KSZ, gK, cbase, b, ipair, th);
    CP_COMMIT();

    for (int ch = 0; ch < 8; ch++) {
        float* cbuf = base + (ch & 1) * BUF;
        float* nbuf = base + ((ch & 1) ^ 1) * BUF;
        if (ch < 7) {
            stage<C>(x, nbuf, nbuf + KSZ, gK, cbase + (ch + 1) * CH, b, ipair, th);
            CP_COMMIT();
            cp_wait<1>();
        } else {
            cp_wait<0>();
        }
        asm volatile("bar.sync %0, 64;" :: "r"(1 + h));
        compute_chunk<C>(cbuf, cbuf + KSZ, ii, j0, tx, acc);
        asm volatile("bar.sync %0, 64;" :: "r"(1 + h));
    }

    // ---- reduction epilogue ----
    const int i = ipair * 2 + ii;
    const int ho = 2 * i + Cf::PY;

    if (h == 1) {   // store partials (cin 32..63)
#pragma unroll
        for (int p = 0; p < 16; p++) {
            const int wo = 2 * (j0 + p) + Cf::PX;
            float v0, v1, v2, v3;
            unpack2(acc[p][0], v0, v1);
            unpack2(acc[p][1], v2, v3);
            float* op = out + (((b * 64 + ho) * 64 + wo) << 6) + 4 * tx;
            *(float4*)op = make_float4(v0, v1, v2, v3);
        }
    }
    __syncthreads();
    if (h == 0) {   // add partial + bias, final store
        float4 bo = *(const float4*)(g_bias + 4 * tx);
#pragma unroll
        for (int p = 0; p < 16; p++) {
            const int wo = 2 * (j0 + p) + Cf::PX;
            float* op = out + (((b * 64 + ho) * 64 + wo) << 6) + 4 * tx;
            float4 o0 = *(const float4*)op;
            float v0, v1, v2, v3;
            unpack2(acc[p][0], v0, v1);
            unpack2(acc[p][1], v2, v3);
            *(float4*)op = make_float4(v0 + bo.x + o0.x, v1 + bo.y + o0.y,
                                       v2 + bo.z + o0.z, v3 + bo.w + o0.w);
        }
    }
}

__global__ __launch_bounds__(128, 3) void qct_main(const float* __restrict__ x,
                                                   float* __restrict__ out) {
    int id = blockIdx.x;
    // heavy class 3 first for wave balance
    if (id < 128)      run_tile<3>(x, out, id);
    else if (id < 256) run_tile<1>(x, out, id - 128);
    else if (id < 384) run_tile<2>(x, out, id - 256);
    else               run_tile<0>(x, out, id - 384);
}

// --------------------------- launch ----------------------------------------

extern "C" void kernel_launch(void* const* d_in, const int* in_sizes, int n_in,
                              void* d_out, int out_size) {
    const float* x  = (const float*)d_in[0];
    const float* fk = (const float*)d_in[1];
    if (n_in >= 2 && in_sizes[0] == 55 * 64 * 64) {  // defensive order check
        const float* tmp = x; x = fk; fk = tmp;
    }
    float* out = (float*)d_out;

    qct_prep<<<(4 * 14 * 4096 + 255) / 256, 256>>>(fk);

    // 2 halves x 2 buffers of (kernel chunk + plain taps), sized for class 3
    const int smem_bytes = 4 * (CH * 14 * 64 + CH * 3 * 34) * 4;  // 63872
    cudaFuncSetAttribute(qct_main, cudaFuncAttributeMaxDynamicSharedMemorySize,
                         smem_bytes);
    qct_main<<<512, 128, smem_bytes>>>(x, out);
}